// round 5
// baseline (speedup 1.0000x reference)
#include <cuda_runtime.h>
#include <cuda_bf16.h>
#include <math.h>
#include <stdint.h>

#define N_WAY     100
#define K_SHOT    10
#define N_SUPPORT 1000
#define N_QUERY   8192
#define F_IN      4096
#define D_EMB     1024
#define EPS_F     1e-6f

#define M_TOT     9216   // 8192 query rows + 1000 support + 24 pad

// ---------------- scratch (static device globals; no allocations) ----------
__device__ __nv_bfloat16 g_Ahi[(size_t)M_TOT * F_IN];
__device__ __nv_bfloat16 g_Alo[(size_t)M_TOT * F_IN];
__device__ __nv_bfloat16 g_Wthi[(size_t)D_EMB * F_IN];
__device__ __nv_bfloat16 g_Wtlo[(size_t)D_EMB * F_IN];
__device__ float g_Z[(size_t)M_TOT * D_EMB];                 // support rows used
__device__ __nv_bfloat16 g_Zqhi[(size_t)N_QUERY * D_EMB];    // query emb hi
__device__ __nv_bfloat16 g_Zqlo[(size_t)N_QUERY * D_EMB];    // query emb lo
__device__ __nv_bfloat16 g_Phi[128 * D_EMB];                 // proto hi (pad 128)
__device__ __nv_bfloat16 g_Plo[128 * D_EMB];                 // proto lo
__device__ float g_p2[128];
__device__ float g_ps[128];
__device__ float g_q2[N_QUERY];
__device__ float g_qs[N_QUERY];
__device__ int   g_order[N_SUPPORT];

// ======================= portable PTX helpers ==============================
__device__ __forceinline__ uint32_t smem_u32(const void* p) {
    uint32_t a;
    asm("{ .reg .u64 t; cvta.to.shared.u64 t, %1; cvt.u32.u64 %0, t; }"
        : "=r"(a) : "l"(p));
    return a;
}
__device__ __forceinline__ void cp_async16(uint32_t dst, const void* src) {
    asm volatile("cp.async.cg.shared.global [%0], [%1], 16;"
                 :: "r"(dst), "l"(src) : "memory");
}
__device__ __forceinline__ void cp_commit() {
    asm volatile("cp.async.commit_group;" ::: "memory");
}
__device__ __forceinline__ void cp_wait1() {
    asm volatile("cp.async.wait_group 1;" ::: "memory");
}
__device__ __forceinline__ void ldmx4(uint32_t* r, uint32_t addr) {
    asm volatile("ldmatrix.sync.aligned.m8n8.x4.shared.b16 {%0,%1,%2,%3}, [%4];"
                 : "=r"(r[0]), "=r"(r[1]), "=r"(r[2]), "=r"(r[3]) : "r"(addr));
}
__device__ __forceinline__ void mma_bf16(float* c, const uint32_t* a, const uint32_t* b) {
    asm volatile(
        "mma.sync.aligned.m16n8k16.row.col.f32.bf16.bf16.f32 "
        "{%0,%1,%2,%3}, {%4,%5,%6,%7}, {%8,%9}, {%0,%1,%2,%3};"
        : "+f"(c[0]), "+f"(c[1]), "+f"(c[2]), "+f"(c[3])
        : "r"(a[0]), "r"(a[1]), "r"(a[2]), "r"(a[3]), "r"(b[0]), "r"(b[1]));
}

// =====================================================================
// Kernel A: split fp32 inputs into bf16 hi/lo
// =====================================================================
__global__ void convert_A(const float* __restrict__ q, const float* __restrict__ s)
{
    size_t i = (size_t)blockIdx.x * blockDim.x + threadIdx.x;
    const size_t total = (size_t)M_TOT * F_IN / 4;
    if (i >= total) return;
    const size_t row = i / (F_IN / 4);
    const size_t seg = i % (F_IN / 4);
    float4 v;
    if (row < N_QUERY)                  v = *(const float4*)(q + row * F_IN + seg * 4);
    else if (row < N_QUERY + N_SUPPORT) v = *(const float4*)(s + (row - N_QUERY) * F_IN + seg * 4);
    else                                v = make_float4(0.f, 0.f, 0.f, 0.f);

    float x[4] = {v.x, v.y, v.z, v.w};
    union B4 { __nv_bfloat16 b[4]; uint2 u; } uh, ul;
    #pragma unroll
    for (int j = 0; j < 4; j++) {
        __nv_bfloat16 h = __float2bfloat16_rn(x[j]);
        uh.b[j] = h;
        ul.b[j] = __float2bfloat16_rn(x[j] - __bfloat162float(h));
    }
    *(uint2*)(g_Ahi + i * 4) = uh.u;
    *(uint2*)(g_Alo + i * 4) = ul.u;
}

// =====================================================================
// Kernel B: transpose W [4096,1024] -> Wt hi/lo [1024,4096] bf16
// =====================================================================
__global__ void convert_W(const float* __restrict__ W)
{
    __shared__ __nv_bfloat16 th[32][33];
    __shared__ __nv_bfloat16 tl[32][33];
    const int k0 = blockIdx.x * 32, n0 = blockIdx.y * 32;
    const int tx = threadIdx.x, ty = threadIdx.y;   // (32, 8)
    #pragma unroll
    for (int i = 0; i < 4; i++) {
        const int kk = ty + i * 8;
        float x = W[(size_t)(k0 + kk) * D_EMB + n0 + tx];
        __nv_bfloat16 h = __float2bfloat16_rn(x);
        th[kk][tx] = h;
        tl[kk][tx] = __float2bfloat16_rn(x - __bfloat162float(h));
    }
    __syncthreads();
    #pragma unroll
    for (int i = 0; i < 4; i++) {
        const int nn = ty + i * 8;
        g_Wthi[(size_t)(n0 + nn) * F_IN + k0 + tx] = th[tx][nn];
        g_Wtlo[(size_t)(n0 + nn) * F_IN + k0 + tx] = tl[tx][nn];
    }
}

// =====================================================================
// Kernel C: bf16x3 tensor-core GEMM, 3-stage cp.async multistage.
// Pass order hh -> lh -> hl (lower peak fragment regs); prefetch issued
// right after the barrier for max copy/compute overlap.
// =====================================================================
#define GM 128
#define GN 256
#define GK 32
#define NCH (F_IN / GK)          // 128
#define ROWB 80                  // 32 bf16 + 8 pad bytes
#define SA_HI 0
#define SA_LO (GM * ROWB)
#define SB_HI (2 * GM * ROWB)
#define SB_LO (2 * GM * ROWB + GN * ROWB)
#define STAGE (2 * GM * ROWB + 2 * GN * ROWB)  // 61440
#define NSTAGE 3
#define GEMM_SMEM (NSTAGE * STAGE)             // 184320

__device__ __forceinline__ void copy_chunk(uint32_t sb, int blockRow, int blockCol,
                                           int c, int tid)
{
    const size_t kc = (size_t)c * GK;
    #pragma unroll
    for (int i = 0; i < 4; i++) {
        const int id  = tid + i * 256;
        const int arr = id >> 9;
        const int rid = (id >> 2) & 127;
        const int seg = id & 3;
        const char* src = (const char*)(arr ? g_Alo : g_Ahi)
                        + ((size_t)(blockRow + rid) * F_IN + kc) * 2 + seg * 16;
        cp_async16(sb + arr * (GM * ROWB) + rid * ROWB + seg * 16, src);
    }
    #pragma unroll
    for (int i = 0; i < 8; i++) {
        const int id  = tid + i * 256;
        const int arr = id >> 10;
        const int rid = (id >> 2) & 255;
        const int seg = id & 3;
        const char* src = (const char*)(arr ? g_Wtlo : g_Wthi)
                        + ((size_t)(blockCol + rid) * F_IN + kc) * 2 + seg * 16;
        cp_async16(sb + SB_HI + arr * (GN * ROWB) + rid * ROWB + seg * 16, src);
    }
}

__global__ __launch_bounds__(256, 1)
void gemm_bf16x3(const float* __restrict__ bias)
{
    extern __shared__ char smem[];
    const uint32_t sbase = smem_u32(smem);
    const int tid = threadIdx.x;
    const int wid = tid >> 5;
    const int l   = tid & 31;
    const int warpM = wid >> 2;
    const int warpN = wid & 3;
    const int blockRow = blockIdx.y * GM;
    const int blockCol = blockIdx.x * GN;

    const uint32_t aOff = (uint32_t)((warpM * 64 + (l & 15)) * ROWB + (l >> 4) * 16);
    uint32_t bOff[4];
    #pragma unroll
    for (int p = 0; p < 4; p++)
        bOff[p] = (uint32_t)(SB_HI + (warpN * 64 + p * 16 + ((l >> 4) & 1) * 8 + (l & 7)) * ROWB
                             + ((l >> 3) & 1) * 16);

    float acc[4][8][4];
    #pragma unroll
    for (int mt = 0; mt < 4; mt++)
        #pragma unroll
        for (int nt = 0; nt < 8; nt++)
            #pragma unroll
            for (int r = 0; r < 4; r++) acc[mt][nt][r] = 0.f;

    copy_chunk(sbase, blockRow, blockCol, 0, tid);
    cp_commit();
    copy_chunk(sbase + STAGE, blockRow, blockCol, 1, tid);
    cp_commit();

    uint32_t stOff = 0;
    uint32_t wrOff = 2 * STAGE;

    for (int c = 0; c < NCH; c++) {
        cp_wait1();
        __syncthreads();

        // prefetch chunk c+2 immediately: full-chunk latency slack
        if (c + 2 < NCH) copy_chunk(sbase + wrOff, blockRow, blockCol, c + 2, tid);
        cp_commit();

        const uint32_t st = sbase + stOff;
        #pragma unroll
        for (int ks = 0; ks < 2; ks++) {
            const uint32_t kb = ks * 32;
            uint32_t aH[4][4], aL[4][4], bH[4][4], bL[4][4];

            #pragma unroll
            for (int mt = 0; mt < 4; mt++) ldmx4(aH[mt], st + aOff + mt * (16 * ROWB) + kb);
            #pragma unroll
            for (int p = 0; p < 4; p++)   ldmx4(bH[p], st + bOff[p] + kb);

            // pass 1: hi * hi
            #pragma unroll
            for (int mt = 0; mt < 4; mt++)
                #pragma unroll
                for (int p = 0; p < 4; p++) {
                    mma_bf16(acc[mt][p * 2 + 0], aH[mt], &bH[p][0]);
                    mma_bf16(acc[mt][p * 2 + 1], aH[mt], &bH[p][2]);
                }

            // pass 2: lo * hi (aL loaded here; bH still live, bL not yet)
            #pragma unroll
            for (int mt = 0; mt < 4; mt++) ldmx4(aL[mt], st + aOff + SA_LO + mt * (16 * ROWB) + kb);
            #pragma unroll
            for (int mt = 0; mt < 4; mt++)
                #pragma unroll
                for (int p = 0; p < 4; p++) {
                    mma_bf16(acc[mt][p * 2 + 0], aL[mt], &bH[p][0]);
                    mma_bf16(acc[mt][p * 2 + 1], aL[mt], &bH[p][2]);
                }

            // pass 3: hi * lo (bH dead, bL replaces it)
            #pragma unroll
            for (int p = 0; p < 4; p++)   ldmx4(bL[p], st + bOff[p] + (GN * ROWB) + kb);
            #pragma unroll
            for (int mt = 0; mt < 4; mt++)
                #pragma unroll
                for (int p = 0; p < 4; p++) {
                    mma_bf16(acc[mt][p * 2 + 0], aH[mt], &bL[p][0]);
                    mma_bf16(acc[mt][p * 2 + 1], aH[mt], &bL[p][2]);
                }
        }

        stOff += STAGE; if (stOff == NSTAGE * STAGE) stOff = 0;
        wrOff += STAGE; if (wrOff == NSTAGE * STAGE) wrOff = 0;
    }

    // epilogue: + bias; query rows -> bf16 hi/lo pair; support rows -> fp32 g_Z
    const bool isQuery = (blockRow < N_QUERY);
    #pragma unroll
    for (int mt = 0; mt < 4; mt++) {
        const int r0 = blockRow + warpM * 64 + mt * 16 + (l >> 2);
        #pragma unroll
        for (int nt = 0; nt < 8; nt++) {
            const int col = blockCol + warpN * 64 + nt * 8 + (l & 3) * 2;
            const float b0 = bias[col], b1 = bias[col + 1];
            const float v00 = acc[mt][nt][0] + b0, v01 = acc[mt][nt][1] + b1;
            const float v10 = acc[mt][nt][2] + b0, v11 = acc[mt][nt][3] + b1;
            if (isQuery) {
                __nv_bfloat16 h00 = __float2bfloat16_rn(v00);
                __nv_bfloat16 h01 = __float2bfloat16_rn(v01);
                __nv_bfloat16 h10 = __float2bfloat16_rn(v10);
                __nv_bfloat16 h11 = __float2bfloat16_rn(v11);
                __nv_bfloat162 lo0, lo1, hi0, hi1;
                hi0.x = h00; hi0.y = h01;
                hi1.x = h10; hi1.y = h11;
                lo0.x = __float2bfloat16_rn(v00 - __bfloat162float(h00));
                lo0.y = __float2bfloat16_rn(v01 - __bfloat162float(h01));
                lo1.x = __float2bfloat16_rn(v10 - __bfloat162float(h10));
                lo1.y = __float2bfloat16_rn(v11 - __bfloat162float(h11));
                *(__nv_bfloat162*)(g_Zqhi + (size_t)r0 * D_EMB + col)       = hi0;
                *(__nv_bfloat162*)(g_Zqlo + (size_t)r0 * D_EMB + col)       = lo0;
                *(__nv_bfloat162*)(g_Zqhi + (size_t)(r0 + 8) * D_EMB + col) = hi1;
                *(__nv_bfloat162*)(g_Zqlo + (size_t)(r0 + 8) * D_EMB + col) = lo1;
            } else {
                *(float2*)(g_Z + (size_t)r0 * D_EMB + col)       = make_float2(v00, v01);
                *(float2*)(g_Z + (size_t)(r0 + 8) * D_EMB + col) = make_float2(v10, v11);
            }
        }
    }
}

// =====================================================================
// Kernel D: stable order — warp per class, ballot compaction
// =====================================================================
__global__ void build_order_kernel(const int* __restrict__ labels)
{
    const int c = blockIdx.x;
    const int l = threadIdx.x;
    int base = 0;
    for (int i0 = 0; i0 < N_SUPPORT; i0 += 32) {
        const int i = i0 + l;
        const bool match = (i < N_SUPPORT) && (labels[i] == c);
        const unsigned m = __ballot_sync(0xFFFFFFFFu, match);
        if (match) {
            const int pos = base + __popc(m & ((1u << l) - 1u));
            if (pos < K_SHOT) g_order[c * K_SHOT + pos] = i;
        }
        base += __popc(m);
    }
}

// =====================================================================
// Kernel E: prototypes (lower median + mean), class stats, bf16 hi/lo out
// =====================================================================
__global__ __launch_bounds__(256)
void proto_kernel()
{
    const int c   = blockIdx.x;
    const int tid = threadIdx.x;
    __shared__ float s_sum[256], s_sum2[256];

    float psum = 0.f, psum2 = 0.f;
    if (c < N_WAY) {
        int idx[K_SHOT];
        #pragma unroll
        for (int j = 0; j < K_SHOT; j++) idx[j] = g_order[c * K_SHOT + j];

        for (int d = tid; d < D_EMB; d += 256) {
            float v[K_SHOT];
            #pragma unroll
            for (int j = 0; j < K_SHOT; j++)
                v[j] = g_Z[(size_t)(N_QUERY + idx[j]) * D_EMB + d];

            float mean = 0.f;
            #pragma unroll
            for (int j = 0; j < K_SHOT; j++) mean += v[j];
            mean *= (1.0f / K_SHOT);

            #pragma unroll
            for (int p = 0; p < K_SHOT - 1; p++)
                #pragma unroll
                for (int q = 0; q < K_SHOT - 1 - p; q++) {
                    float lo = fminf(v[q], v[q + 1]);
                    float hi = fmaxf(v[q], v[q + 1]);
                    v[q] = lo; v[q + 1] = hi;
                }
            const float med = v[(K_SHOT - 1) / 2];
            const float zt  = 0.5f * (med + mean);
            __nv_bfloat16 h = __float2bfloat16_rn(zt);
            g_Phi[(size_t)c * D_EMB + d] = h;
            g_Plo[(size_t)c * D_EMB + d] = __float2bfloat16_rn(zt - __bfloat162float(h));
            psum += zt; psum2 += zt * zt;
        }
    } else {
        for (int d = tid; d < D_EMB; d += 256) {
            g_Phi[(size_t)c * D_EMB + d] = __float2bfloat16_rn(0.f);
            g_Plo[(size_t)c * D_EMB + d] = __float2bfloat16_rn(0.f);
        }
    }

    s_sum[tid] = psum; s_sum2[tid] = psum2;
    __syncthreads();
    for (int s = 128; s > 0; s >>= 1) {
        if (tid < s) { s_sum[tid] += s_sum[tid + s]; s_sum2[tid] += s_sum2[tid + s]; }
        __syncthreads();
    }
    if (tid == 0 && c < N_WAY) { g_ps[c] = s_sum[0]; g_p2[c] = s_sum2[0]; }
}

// =====================================================================
// Kernel F: per-query-row stats from bf16 hi/lo — warp per row
// =====================================================================
__global__ __launch_bounds__(256)
void qstats_kernel()
{
    const int warp = (blockIdx.x * blockDim.x + threadIdx.x) >> 5;
    const int l    = threadIdx.x & 31;
    if (warp >= N_QUERY) return;
    const size_t base = (size_t)warp * D_EMB;
    float s = 0.f, s2 = 0.f;
    #pragma unroll
    for (int i = 0; i < 4; i++) {
        const size_t off = base + i * 256 + l * 8;
        uint4 uh = *(const uint4*)(g_Zqhi + off);
        uint4 ul = *(const uint4*)(g_Zqlo + off);
        const uint32_t hw[4] = {uh.x, uh.y, uh.z, uh.w};
        const uint32_t lw[4] = {ul.x, ul.y, ul.z, ul.w};
        #pragma unroll
        for (int j = 0; j < 4; j++) {
            __nv_bfloat162 h2 = *(const __nv_bfloat162*)&hw[j];
            __nv_bfloat162 l2 = *(const __nv_bfloat162*)&lw[j];
            float z0 = __bfloat162float(h2.x) + __bfloat162float(l2.x);
            float z1 = __bfloat162float(h2.y) + __bfloat162float(l2.y);
            s  += z0 + z1;
            s2 += z0 * z0 + z1 * z1;
        }
    }
    #pragma unroll
    for (int off = 16; off > 0; off >>= 1) {
        s  += __shfl_xor_sync(0xFFFFFFFFu, s,  off);
        s2 += __shfl_xor_sync(0xFFFFFFFFu, s2, off);
    }
    if (l == 0) { g_qs[warp] = s; g_q2[warp] = s2; }
}

// =====================================================================
// Kernel G: distance matrix — bf16x3 mma GEMM (128 x 128pad x 1024)
// with fused PairwiseDistance-eps epilogue.
// =====================================================================
#define D2K 32
#define NCH2 (D_EMB / D2K)                 // 32
#define S2A_HI 0
#define S2A_LO (128 * ROWB)
#define S2B_HI (2 * 128 * ROWB)
#define S2B_LO (3 * 128 * ROWB)
#define STAGE2 (4 * 128 * ROWB)            // 40960
#define DIST_SMEM (3 * STAGE2)             // 122880

__device__ __forceinline__ void copy_chunk2(uint32_t sb, int blockRow, int c, int tid)
{
    const size_t kb = (size_t)c * D2K * 2;   // byte offset within a row
    #pragma unroll
    for (int i = 0; i < 2; i++) {            // A hi
        const int id = tid + i * 256, rid = id >> 2, seg = id & 3;
        cp_async16(sb + S2A_HI + rid * ROWB + seg * 16,
                   (const char*)g_Zqhi + ((size_t)(blockRow + rid) * D_EMB) * 2 + kb + seg * 16);
    }
    #pragma unroll
    for (int i = 0; i < 2; i++) {            // A lo
        const int id = tid + i * 256, rid = id >> 2, seg = id & 3;
        cp_async16(sb + S2A_LO + rid * ROWB + seg * 16,
                   (const char*)g_Zqlo + ((size_t)(blockRow + rid) * D_EMB) * 2 + kb + seg * 16);
    }
    #pragma unroll
    for (int i = 0; i < 2; i++) {            // B hi
        const int id = tid + i * 256, rid = id >> 2, seg = id & 3;
        cp_async16(sb + S2B_HI + rid * ROWB + seg * 16,
                   (const char*)g_Phi + ((size_t)rid * D_EMB) * 2 + kb + seg * 16);
    }
    #pragma unroll
    for (int i = 0; i < 2; i++) {            // B lo
        const int id = tid + i * 256, rid = id >> 2, seg = id & 3;
        cp_async16(sb + S2B_LO + rid * ROWB + seg * 16,
                   (const char*)g_Plo + ((size_t)rid * D_EMB) * 2 + kb + seg * 16);
    }
}

__global__ __launch_bounds__(256, 1)
void dist_mma_kernel(float* __restrict__ out)
{
    extern __shared__ char smem[];
    const uint32_t sbase = smem_u32(smem);
    const int tid = threadIdx.x;
    const int wid = tid >> 5;
    const int l   = tid & 31;
    const int warpM = wid >> 1;          // 0..3  -> 32 rows
    const int warpN = wid & 1;           // 0..1  -> 64 cols
    const int blockRow = blockIdx.x * 128;

    const uint32_t aOff = (uint32_t)((warpM * 32 + (l & 15)) * ROWB + (l >> 4) * 16);
    uint32_t bOff[4];
    #pragma unroll
    for (int p = 0; p < 4; p++)
        bOff[p] = (uint32_t)(S2B_HI + (warpN * 64 + p * 16 + ((l >> 4) & 1) * 8 + (l & 7)) * ROWB
                             + ((l >> 3) & 1) * 16);

    float acc[2][8][4];
    #pragma unroll
    for (int mt = 0; mt < 2; mt++)
        #pragma unroll
        for (int nt = 0; nt < 8; nt++)
            #pragma unroll
            for (int r = 0; r < 4; r++) acc[mt][nt][r] = 0.f;

    copy_chunk2(sbase, blockRow, 0, tid);
    cp_commit();
    copy_chunk2(sbase + STAGE2, blockRow, 1, tid);
    cp_commit();

    uint32_t stOff = 0;
    uint32_t wrOff = 2 * STAGE2;

    for (int c = 0; c < NCH2; c++) {
        cp_wait1();
        __syncthreads();
        if (c + 2 < NCH2) copy_chunk2(sbase + wrOff, blockRow, c + 2, tid);
        cp_commit();

        const uint32_t st = sbase + stOff;
        #pragma unroll
        for (int ks = 0; ks < 2; ks++) {
            const uint32_t kb = ks * 32;
            uint32_t aH[2][4], aL[2][4], bH[4][4], bL[4][4];

            #pragma unroll
            for (int mt = 0; mt < 2; mt++) ldmx4(aH[mt], st + aOff + mt * (16 * ROWB) + kb);
            #pragma unroll
            for (int p = 0; p < 4; p++)   ldmx4(bH[p], st + bOff[p] + kb);

            #pragma unroll
            for (int mt = 0; mt < 2; mt++)
                #pragma unroll
                for (int p = 0; p < 4; p++) {
                    mma_bf16(acc[mt][p * 2 + 0], aH[mt], &bH[p][0]);
                    mma_bf16(acc[mt][p * 2 + 1], aH[mt], &bH[p][2]);
                }

            #pragma unroll
            for (int mt = 0; mt < 2; mt++) ldmx4(aL[mt], st + aOff + (S2A_LO - S2A_HI) + mt * (16 * ROWB) + kb);
            #pragma unroll
            for (int mt = 0; mt < 2; mt++)
                #pragma unroll
                for (int p = 0; p < 4; p++) {
                    mma_bf16(acc[mt][p * 2 + 0], aL[mt], &bH[p][0]);
                    mma_bf16(acc[mt][p * 2 + 1], aL[mt], &bH[p][2]);
                }

            #pragma unroll
            for (int p = 0; p < 4; p++)   ldmx4(bL[p], st + bOff[p] + (128 * ROWB) + kb);
            #pragma unroll
            for (int mt = 0; mt < 2; mt++)
                #pragma unroll
                for (int p = 0; p < 4; p++) {
                    mma_bf16(acc[mt][p * 2 + 0], aH[mt], &bL[p][0]);
                    mma_bf16(acc[mt][p * 2 + 1], aH[mt], &bL[p][2]);
                }
        }

        stOff += STAGE2; if (stOff == 3 * STAGE2) stOff = 0;
        wrOff += STAGE2; if (wrOff == 3 * STAGE2) wrOff = 0;
    }

    // fused distance epilogue
    const float deps2 = (float)D_EMB * EPS_F * EPS_F;
    #pragma unroll
    for (int mt = 0; mt < 2; mt++) {
        const int r0 = blockRow + warpM * 32 + mt * 16 + (l >> 2);
        const float q2a = g_q2[r0],     qsa = g_qs[r0];
        const float q2b = g_q2[r0 + 8], qsb = g_qs[r0 + 8];
        #pragma unroll
        for (int nt = 0; nt < 8; nt++) {
            const int c0 = warpN * 64 + nt * 8 + (l & 3) * 2;
            #pragma unroll
            for (int jj = 0; jj < 2; jj++) {
                const int c = c0 + jj;
                if (c < N_WAY) {
                    const float p2v = g_p2[c], psv = g_ps[c];
                    float sqa = q2a + p2v - 2.0f * acc[mt][nt][jj]
                              + 2.0f * EPS_F * (qsa - psv) + deps2;
                    float sqb = q2b + p2v - 2.0f * acc[mt][nt][2 + jj]
                              + 2.0f * EPS_F * (qsb - psv) + deps2;
                    out[(size_t)r0 * N_WAY + c]       = -sqrtf(fmaxf(sqa, 0.0f));
                    out[(size_t)(r0 + 8) * N_WAY + c] = -sqrtf(fmaxf(sqb, 0.0f));
                }
            }
        }
    }
}

// =====================================================================
// launch
// =====================================================================
extern "C" void kernel_launch(void* const* d_in, const int* in_sizes, int n_in,
                              void* d_out, int out_size)
{
    const float* support = (const float*)d_in[0];
    const int*   labels  = (const int*)  d_in[1];
    const float* query   = (const float*)d_in[2];
    const float* W       = (const float*)d_in[3];
    const float* b       = (const float*)d_in[4];
    float*       out     = (float*)d_out;

    cudaFuncSetAttribute(gemm_bf16x3,
                         cudaFuncAttributeMaxDynamicSharedMemorySize, GEMM_SMEM);
    cudaFuncSetAttribute(dist_mma_kernel,
                         cudaFuncAttributeMaxDynamicSharedMemorySize, DIST_SMEM);

    {
        const size_t total = (size_t)M_TOT * F_IN / 4;
        convert_A<<<(unsigned)((total + 255) / 256), 256>>>(query, support);
    }
    convert_W<<<dim3(F_IN / 32, D_EMB / 32), dim3(32, 8)>>>(W);
    build_order_kernel<<<N_WAY, 32>>>(labels);

    gemm_bf16x3<<<dim3(D_EMB / GN, M_TOT / GM), 256, GEMM_SMEM>>>(b);

    proto_kernel<<<128, 256>>>();
    qstats_kernel<<<N_QUERY / 8, 256>>>();
    dist_mma_kernel<<<N_QUERY / 128, 256, DIST_SMEM>>>(out);
}

// round 6
// speedup vs baseline: 1.0026x; 1.0026x over previous
#include <cuda_runtime.h>
#include <cuda_bf16.h>
#include <math.h>
#include <stdint.h>

#define N_WAY     100
#define K_SHOT    10
#define N_SUPPORT 1000
#define N_QUERY   8192
#define F_IN      4096
#define D_EMB     1024
#define EPS_F     1e-6f

#define M_TOT     9216   // 8192 query rows + 1000 support + 24 pad

// ---------------- scratch (static device globals; no allocations) ----------
__device__ __nv_bfloat16 g_Ahi[(size_t)M_TOT * F_IN];
__device__ __nv_bfloat16 g_Alo[(size_t)M_TOT * F_IN];
__device__ __nv_bfloat16 g_Wthi[(size_t)D_EMB * F_IN];
__device__ __nv_bfloat16 g_Wtlo[(size_t)D_EMB * F_IN];
__device__ float g_Z[(size_t)M_TOT * D_EMB];                 // support rows used
__device__ __nv_bfloat16 g_Zqhi[(size_t)N_QUERY * D_EMB];    // query emb hi
__device__ __nv_bfloat16 g_Zqlo[(size_t)N_QUERY * D_EMB];    // query emb lo
__device__ __nv_bfloat16 g_Phi[128 * D_EMB];                 // proto hi (pad 128)
__device__ __nv_bfloat16 g_Plo[128 * D_EMB];                 // proto lo
__device__ float g_p2[128];
__device__ float g_ps[128];
__device__ float g_q2[N_QUERY];
__device__ float g_qs[N_QUERY];
__device__ int   g_order[N_SUPPORT];

// ======================= portable PTX helpers ==============================
__device__ __forceinline__ uint32_t smem_u32(const void* p) {
    uint32_t a;
    asm("{ .reg .u64 t; cvta.to.shared.u64 t, %1; cvt.u32.u64 %0, t; }"
        : "=r"(a) : "l"(p));
    return a;
}
__device__ __forceinline__ void cp_async16(uint32_t dst, const void* src) {
    asm volatile("cp.async.cg.shared.global [%0], [%1], 16;"
                 :: "r"(dst), "l"(src) : "memory");
}
__device__ __forceinline__ void cp_commit() {
    asm volatile("cp.async.commit_group;" ::: "memory");
}
__device__ __forceinline__ void cp_wait1() {
    asm volatile("cp.async.wait_group 1;" ::: "memory");
}
__device__ __forceinline__ void ldmx4(uint32_t* r, uint32_t addr) {
    asm volatile("ldmatrix.sync.aligned.m8n8.x4.shared.b16 {%0,%1,%2,%3}, [%4];"
                 : "=r"(r[0]), "=r"(r[1]), "=r"(r[2]), "=r"(r[3]) : "r"(addr));
}
__device__ __forceinline__ void mma_bf16(float* c, const uint32_t* a, const uint32_t* b) {
    asm volatile(
        "mma.sync.aligned.m16n8k16.row.col.f32.bf16.bf16.f32 "
        "{%0,%1,%2,%3}, {%4,%5,%6,%7}, {%8,%9}, {%0,%1,%2,%3};"
        : "+f"(c[0]), "+f"(c[1]), "+f"(c[2]), "+f"(c[3])
        : "r"(a[0]), "r"(a[1]), "r"(a[2]), "r"(a[3]), "r"(b[0]), "r"(b[1]));
}

// =====================================================================
// Kernel A: split fp32 inputs into bf16 hi/lo
// =====================================================================
__global__ void convert_A(const float* __restrict__ q, const float* __restrict__ s)
{
    size_t i = (size_t)blockIdx.x * blockDim.x + threadIdx.x;
    const size_t total = (size_t)M_TOT * F_IN / 4;
    if (i >= total) return;
    const size_t row = i / (F_IN / 4);
    const size_t seg = i % (F_IN / 4);
    float4 v;
    if (row < N_QUERY)                  v = *(const float4*)(q + row * F_IN + seg * 4);
    else if (row < N_QUERY + N_SUPPORT) v = *(const float4*)(s + (row - N_QUERY) * F_IN + seg * 4);
    else                                v = make_float4(0.f, 0.f, 0.f, 0.f);

    float x[4] = {v.x, v.y, v.z, v.w};
    union B4 { __nv_bfloat16 b[4]; uint2 u; } uh, ul;
    #pragma unroll
    for (int j = 0; j < 4; j++) {
        __nv_bfloat16 h = __float2bfloat16_rn(x[j]);
        uh.b[j] = h;
        ul.b[j] = __float2bfloat16_rn(x[j] - __bfloat162float(h));
    }
    *(uint2*)(g_Ahi + i * 4) = uh.u;
    *(uint2*)(g_Alo + i * 4) = ul.u;
}

// =====================================================================
// Kernel B: transpose W [4096,1024] -> Wt hi/lo [1024,4096] bf16
// =====================================================================
__global__ void convert_W(const float* __restrict__ W)
{
    __shared__ __nv_bfloat16 th[32][33];
    __shared__ __nv_bfloat16 tl[32][33];
    const int k0 = blockIdx.x * 32, n0 = blockIdx.y * 32;
    const int tx = threadIdx.x, ty = threadIdx.y;   // (32, 8)
    #pragma unroll
    for (int i = 0; i < 4; i++) {
        const int kk = ty + i * 8;
        float x = W[(size_t)(k0 + kk) * D_EMB + n0 + tx];
        __nv_bfloat16 h = __float2bfloat16_rn(x);
        th[kk][tx] = h;
        tl[kk][tx] = __float2bfloat16_rn(x - __bfloat162float(h));
    }
    __syncthreads();
    #pragma unroll
    for (int i = 0; i < 4; i++) {
        const int nn = ty + i * 8;
        g_Wthi[(size_t)(n0 + nn) * F_IN + k0 + tx] = th[tx][nn];
        g_Wtlo[(size_t)(n0 + nn) * F_IN + k0 + tx] = tl[tx][nn];
    }
}

// =====================================================================
// Kernel C: bf16x3 tensor-core GEMM, 3-stage cp.async multistage.
// 512 threads / 16 warps (4 per SMSP) for latency hiding; warp tile 32x64.
// Pass order hh -> lh -> hl keeps peak live fragments at 32 regs.
// =====================================================================
#define GM 128
#define GN 256
#define GK 32
#define NTHR 512
#define NCH (F_IN / GK)          // 128
#define ROWB 80                  // 32 bf16 + 8 pad bytes
#define SA_HI 0
#define SA_LO (GM * ROWB)
#define SB_HI (2 * GM * ROWB)
#define SB_LO (2 * GM * ROWB + GN * ROWB)
#define STAGE (2 * GM * ROWB + 2 * GN * ROWB)  // 61440
#define NSTAGE 3
#define GEMM_SMEM (NSTAGE * STAGE)             // 184320

__device__ __forceinline__ void copy_chunk(uint32_t sb, int blockRow, int blockCol,
                                           int c, int tid)
{
    const size_t kc = (size_t)c * GK;
    // A hi+lo: 1024 x 16B, 512 threads -> 2 iters
    #pragma unroll
    for (int i = 0; i < 2; i++) {
        const int id  = tid + i * NTHR;
        const int arr = id >> 9;
        const int rid = (id >> 2) & 127;
        const int seg = id & 3;
        const char* src = (const char*)(arr ? g_Alo : g_Ahi)
                        + ((size_t)(blockRow + rid) * F_IN + kc) * 2 + seg * 16;
        cp_async16(sb + arr * (GM * ROWB) + rid * ROWB + seg * 16, src);
    }
    // B hi+lo: 2048 x 16B -> 4 iters
    #pragma unroll
    for (int i = 0; i < 4; i++) {
        const int id  = tid + i * NTHR;
        const int arr = id >> 10;
        const int rid = (id >> 2) & 255;
        const int seg = id & 3;
        const char* src = (const char*)(arr ? g_Wtlo : g_Wthi)
                        + ((size_t)(blockCol + rid) * F_IN + kc) * 2 + seg * 16;
        cp_async16(sb + SB_HI + arr * (GN * ROWB) + rid * ROWB + seg * 16, src);
    }
}

__global__ __launch_bounds__(NTHR, 1)
void gemm_bf16x3(const float* __restrict__ bias)
{
    extern __shared__ char smem[];
    const uint32_t sbase = smem_u32(smem);
    const int tid = threadIdx.x;
    const int wid = tid >> 5;
    const int l   = tid & 31;
    const int warpM = wid >> 2;          // 0..3 -> 32-row strip
    const int warpN = wid & 3;           // 0..3 -> 64-col strip
    const int blockRow = blockIdx.y * GM;
    const int blockCol = blockIdx.x * GN;

    // A fragment ldmatrix base: m16 tile, lane l -> row (l&15), k-half (l>>4)
    const uint32_t aOff = (uint32_t)((warpM * 32 + (l & 15)) * ROWB + (l >> 4) * 16);
    // B tile-pair bases: 16 cols per p
    uint32_t bOff[4];
    #pragma unroll
    for (int p = 0; p < 4; p++)
        bOff[p] = (uint32_t)(SB_HI + (warpN * 64 + p * 16 + ((l >> 4) & 1) * 8 + (l & 7)) * ROWB
                             + ((l >> 3) & 1) * 16);

    float acc[2][8][4];
    #pragma unroll
    for (int mt = 0; mt < 2; mt++)
        #pragma unroll
        for (int nt = 0; nt < 8; nt++)
            #pragma unroll
            for (int r = 0; r < 4; r++) acc[mt][nt][r] = 0.f;

    copy_chunk(sbase, blockRow, blockCol, 0, tid);
    cp_commit();
    copy_chunk(sbase + STAGE, blockRow, blockCol, 1, tid);
    cp_commit();

    uint32_t stOff = 0;
    uint32_t wrOff = 2 * STAGE;

    for (int c = 0; c < NCH; c++) {
        cp_wait1();
        __syncthreads();

        if (c + 2 < NCH) copy_chunk(sbase + wrOff, blockRow, blockCol, c + 2, tid);
        cp_commit();

        const uint32_t st = sbase + stOff;
        #pragma unroll
        for (int ks = 0; ks < 2; ks++) {
            const uint32_t kb = ks * 32;
            uint32_t aH[2][4], aL[2][4], bH[4][4], bL[4][4];

            #pragma unroll
            for (int mt = 0; mt < 2; mt++) ldmx4(aH[mt], st + aOff + mt * (16 * ROWB) + kb);
            #pragma unroll
            for (int p = 0; p < 4; p++)   ldmx4(bH[p], st + bOff[p] + kb);

            // pass 1: hi * hi
            #pragma unroll
            for (int mt = 0; mt < 2; mt++)
                #pragma unroll
                for (int p = 0; p < 4; p++) {
                    mma_bf16(acc[mt][p * 2 + 0], aH[mt], &bH[p][0]);
                    mma_bf16(acc[mt][p * 2 + 1], aH[mt], &bH[p][2]);
                }

            // pass 2: lo * hi
            #pragma unroll
            for (int mt = 0; mt < 2; mt++) ldmx4(aL[mt], st + aOff + SA_LO + mt * (16 * ROWB) + kb);
            #pragma unroll
            for (int mt = 0; mt < 2; mt++)
                #pragma unroll
                for (int p = 0; p < 4; p++) {
                    mma_bf16(acc[mt][p * 2 + 0], aL[mt], &bH[p][0]);
                    mma_bf16(acc[mt][p * 2 + 1], aL[mt], &bH[p][2]);
                }

            // pass 3: hi * lo
            #pragma unroll
            for (int p = 0; p < 4; p++)   ldmx4(bL[p], st + bOff[p] + (GN * ROWB) + kb);
            #pragma unroll
            for (int mt = 0; mt < 2; mt++)
                #pragma unroll
                for (int p = 0; p < 4; p++) {
                    mma_bf16(acc[mt][p * 2 + 0], aH[mt], &bL[p][0]);
                    mma_bf16(acc[mt][p * 2 + 1], aH[mt], &bL[p][2]);
                }
        }

        stOff += STAGE; if (stOff == NSTAGE * STAGE) stOff = 0;
        wrOff += STAGE; if (wrOff == NSTAGE * STAGE) wrOff = 0;
    }

    // epilogue: + bias; query rows -> bf16 hi/lo pair; support rows -> fp32 g_Z
    const bool isQuery = (blockRow < N_QUERY);
    #pragma unroll
    for (int mt = 0; mt < 2; mt++) {
        const int r0 = blockRow + warpM * 32 + mt * 16 + (l >> 2);
        #pragma unroll
        for (int nt = 0; nt < 8; nt++) {
            const int col = blockCol + warpN * 64 + nt * 8 + (l & 3) * 2;
            const float b0 = bias[col], b1 = bias[col + 1];
            const float v00 = acc[mt][nt][0] + b0, v01 = acc[mt][nt][1] + b1;
            const float v10 = acc[mt][nt][2] + b0, v11 = acc[mt][nt][3] + b1;
            if (isQuery) {
                __nv_bfloat16 h00 = __float2bfloat16_rn(v00);
                __nv_bfloat16 h01 = __float2bfloat16_rn(v01);
                __nv_bfloat16 h10 = __float2bfloat16_rn(v10);
                __nv_bfloat16 h11 = __float2bfloat16_rn(v11);
                __nv_bfloat162 lo0, lo1, hi0, hi1;
                hi0.x = h00; hi0.y = h01;
                hi1.x = h10; hi1.y = h11;
                lo0.x = __float2bfloat16_rn(v00 - __bfloat162float(h00));
                lo0.y = __float2bfloat16_rn(v01 - __bfloat162float(h01));
                lo1.x = __float2bfloat16_rn(v10 - __bfloat162float(h10));
                lo1.y = __float2bfloat16_rn(v11 - __bfloat162float(h11));
                *(__nv_bfloat162*)(g_Zqhi + (size_t)r0 * D_EMB + col)       = hi0;
                *(__nv_bfloat162*)(g_Zqlo + (size_t)r0 * D_EMB + col)       = lo0;
                *(__nv_bfloat162*)(g_Zqhi + (size_t)(r0 + 8) * D_EMB + col) = hi1;
                *(__nv_bfloat162*)(g_Zqlo + (size_t)(r0 + 8) * D_EMB + col) = lo1;
            } else {
                *(float2*)(g_Z + (size_t)r0 * D_EMB + col)       = make_float2(v00, v01);
                *(float2*)(g_Z + (size_t)(r0 + 8) * D_EMB + col) = make_float2(v10, v11);
            }
        }
    }
}

// =====================================================================
// Kernel D: stable order — warp per class, ballot compaction
// =====================================================================
__global__ void build_order_kernel(const int* __restrict__ labels)
{
    const int c = blockIdx.x;
    const int l = threadIdx.x;
    int base = 0;
    for (int i0 = 0; i0 < N_SUPPORT; i0 += 32) {
        const int i = i0 + l;
        const bool match = (i < N_SUPPORT) && (labels[i] == c);
        const unsigned m = __ballot_sync(0xFFFFFFFFu, match);
        if (match) {
            const int pos = base + __popc(m & ((1u << l) - 1u));
            if (pos < K_SHOT) g_order[c * K_SHOT + pos] = i;
        }
        base += __popc(m);
    }
}

// =====================================================================
// Kernel E: prototypes (lower median + mean), class stats, bf16 hi/lo out
// =====================================================================
__global__ __launch_bounds__(256)
void proto_kernel()
{
    const int c   = blockIdx.x;
    const int tid = threadIdx.x;
    __shared__ float s_sum[256], s_sum2[256];

    float psum = 0.f, psum2 = 0.f;
    if (c < N_WAY) {
        int idx[K_SHOT];
        #pragma unroll
        for (int j = 0; j < K_SHOT; j++) idx[j] = g_order[c * K_SHOT + j];

        for (int d = tid; d < D_EMB; d += 256) {
            float v[K_SHOT];
            #pragma unroll
            for (int j = 0; j < K_SHOT; j++)
                v[j] = g_Z[(size_t)(N_QUERY + idx[j]) * D_EMB + d];

            float mean = 0.f;
            #pragma unroll
            for (int j = 0; j < K_SHOT; j++) mean += v[j];
            mean *= (1.0f / K_SHOT);

            #pragma unroll
            for (int p = 0; p < K_SHOT - 1; p++)
                #pragma unroll
                for (int q = 0; q < K_SHOT - 1 - p; q++) {
                    float lo = fminf(v[q], v[q + 1]);
                    float hi = fmaxf(v[q], v[q + 1]);
                    v[q] = lo; v[q + 1] = hi;
                }
            const float med = v[(K_SHOT - 1) / 2];
            const float zt  = 0.5f * (med + mean);
            __nv_bfloat16 h = __float2bfloat16_rn(zt);
            g_Phi[(size_t)c * D_EMB + d] = h;
            g_Plo[(size_t)c * D_EMB + d] = __float2bfloat16_rn(zt - __bfloat162float(h));
            psum += zt; psum2 += zt * zt;
        }
    } else {
        for (int d = tid; d < D_EMB; d += 256) {
            g_Phi[(size_t)c * D_EMB + d] = __float2bfloat16_rn(0.f);
            g_Plo[(size_t)c * D_EMB + d] = __float2bfloat16_rn(0.f);
        }
    }

    s_sum[tid] = psum; s_sum2[tid] = psum2;
    __syncthreads();
    for (int s = 128; s > 0; s >>= 1) {
        if (tid < s) { s_sum[tid] += s_sum[tid + s]; s_sum2[tid] += s_sum2[tid + s]; }
        __syncthreads();
    }
    if (tid == 0 && c < N_WAY) { g_ps[c] = s_sum[0]; g_p2[c] = s_sum2[0]; }
}

// =====================================================================
// Kernel F: per-query-row stats from bf16 hi/lo — warp per row
// =====================================================================
__global__ __launch_bounds__(256)
void qstats_kernel()
{
    const int warp = (blockIdx.x * blockDim.x + threadIdx.x) >> 5;
    const int l    = threadIdx.x & 31;
    if (warp >= N_QUERY) return;
    const size_t base = (size_t)warp * D_EMB;
    float s = 0.f, s2 = 0.f;
    #pragma unroll
    for (int i = 0; i < 4; i++) {
        const size_t off = base + i * 256 + l * 8;
        uint4 uh = *(const uint4*)(g_Zqhi + off);
        uint4 ul = *(const uint4*)(g_Zqlo + off);
        const uint32_t hw[4] = {uh.x, uh.y, uh.z, uh.w};
        const uint32_t lw[4] = {ul.x, ul.y, ul.z, ul.w};
        #pragma unroll
        for (int j = 0; j < 4; j++) {
            __nv_bfloat162 h2 = *(const __nv_bfloat162*)&hw[j];
            __nv_bfloat162 l2 = *(const __nv_bfloat162*)&lw[j];
            float z0 = __bfloat162float(h2.x) + __bfloat162float(l2.x);
            float z1 = __bfloat162float(h2.y) + __bfloat162float(l2.y);
            s  += z0 + z1;
            s2 += z0 * z0 + z1 * z1;
        }
    }
    #pragma unroll
    for (int off = 16; off > 0; off >>= 1) {
        s  += __shfl_xor_sync(0xFFFFFFFFu, s,  off);
        s2 += __shfl_xor_sync(0xFFFFFFFFu, s2, off);
    }
    if (l == 0) { g_qs[warp] = s; g_q2[warp] = s2; }
}

// =====================================================================
// Kernel G: distance matrix — bf16x3 mma GEMM (128 x 128pad x 1024)
// with fused PairwiseDistance-eps epilogue.
// =====================================================================
#define D2K 32
#define NCH2 (D_EMB / D2K)                 // 32
#define S2A_HI 0
#define S2A_LO (128 * ROWB)
#define S2B_HI (2 * 128 * ROWB)
#define S2B_LO (3 * 128 * ROWB)
#define STAGE2 (4 * 128 * ROWB)            // 40960
#define DIST_SMEM (3 * STAGE2)             // 122880

__device__ __forceinline__ void copy_chunk2(uint32_t sb, int blockRow, int c, int tid)
{
    const size_t kb = (size_t)c * D2K * 2;
    #pragma unroll
    for (int i = 0; i < 2; i++) {
        const int id = tid + i * 256, rid = id >> 2, seg = id & 3;
        cp_async16(sb + S2A_HI + rid * ROWB + seg * 16,
                   (const char*)g_Zqhi + ((size_t)(blockRow + rid) * D_EMB) * 2 + kb + seg * 16);
    }
    #pragma unroll
    for (int i = 0; i < 2; i++) {
        const int id = tid + i * 256, rid = id >> 2, seg = id & 3;
        cp_async16(sb + S2A_LO + rid * ROWB + seg * 16,
                   (const char*)g_Zqlo + ((size_t)(blockRow + rid) * D_EMB) * 2 + kb + seg * 16);
    }
    #pragma unroll
    for (int i = 0; i < 2; i++) {
        const int id = tid + i * 256, rid = id >> 2, seg = id & 3;
        cp_async16(sb + S2B_HI + rid * ROWB + seg * 16,
                   (const char*)g_Phi + ((size_t)rid * D_EMB) * 2 + kb + seg * 16);
    }
    #pragma unroll
    for (int i = 0; i < 2; i++) {
        const int id = tid + i * 256, rid = id >> 2, seg = id & 3;
        cp_async16(sb + S2B_LO + rid * ROWB + seg * 16,
                   (const char*)g_Plo + ((size_t)rid * D_EMB) * 2 + kb + seg * 16);
    }
}

__global__ __launch_bounds__(256, 1)
void dist_mma_kernel(float* __restrict__ out)
{
    extern __shared__ char smem[];
    const uint32_t sbase = smem_u32(smem);
    const int tid = threadIdx.x;
    const int wid = tid >> 5;
    const int l   = tid & 31;
    const int warpM = wid >> 1;
    const int warpN = wid & 1;
    const int blockRow = blockIdx.x * 128;

    const uint32_t aOff = (uint32_t)((warpM * 32 + (l & 15)) * ROWB + (l >> 4) * 16);
    uint32_t bOff[4];
    #pragma unroll
    for (int p = 0; p < 4; p++)
        bOff[p] = (uint32_t)(S2B_HI + (warpN * 64 + p * 16 + ((l >> 4) & 1) * 8 + (l & 7)) * ROWB
                             + ((l >> 3) & 1) * 16);

    float acc[2][8][4];
    #pragma unroll
    for (int mt = 0; mt < 2; mt++)
        #pragma unroll
        for (int nt = 0; nt < 8; nt++)
            #pragma unroll
            for (int r = 0; r < 4; r++) acc[mt][nt][r] = 0.f;

    copy_chunk2(sbase, blockRow, 0, tid);
    cp_commit();
    copy_chunk2(sbase + STAGE2, blockRow, 1, tid);
    cp_commit();

    uint32_t stOff = 0;
    uint32_t wrOff = 2 * STAGE2;

    for (int c = 0; c < NCH2; c++) {
        cp_wait1();
        __syncthreads();
        if (c + 2 < NCH2) copy_chunk2(sbase + wrOff, blockRow, c + 2, tid);
        cp_commit();

        const uint32_t st = sbase + stOff;
        #pragma unroll
        for (int ks = 0; ks < 2; ks++) {
            const uint32_t kb = ks * 32;
            uint32_t aH[2][4], aL[2][4], bH[4][4], bL[4][4];

            #pragma unroll
            for (int mt = 0; mt < 2; mt++) ldmx4(aH[mt], st + aOff + mt * (16 * ROWB) + kb);
            #pragma unroll
            for (int p = 0; p < 4; p++)   ldmx4(bH[p], st + bOff[p] + kb);

            #pragma unroll
            for (int mt = 0; mt < 2; mt++)
                #pragma unroll
                for (int p = 0; p < 4; p++) {
                    mma_bf16(acc[mt][p * 2 + 0], aH[mt], &bH[p][0]);
                    mma_bf16(acc[mt][p * 2 + 1], aH[mt], &bH[p][2]);
                }

            #pragma unroll
            for (int mt = 0; mt < 2; mt++) ldmx4(aL[mt], st + aOff + (S2A_LO - S2A_HI) + mt * (16 * ROWB) + kb);
            #pragma unroll
            for (int mt = 0; mt < 2; mt++)
                #pragma unroll
                for (int p = 0; p < 4; p++) {
                    mma_bf16(acc[mt][p * 2 + 0], aL[mt], &bH[p][0]);
                    mma_bf16(acc[mt][p * 2 + 1], aL[mt], &bH[p][2]);
                }

            #pragma unroll
            for (int p = 0; p < 4; p++)   ldmx4(bL[p], st + bOff[p] + (128 * ROWB) + kb);
            #pragma unroll
            for (int mt = 0; mt < 2; mt++)
                #pragma unroll
                for (int p = 0; p < 4; p++) {
                    mma_bf16(acc[mt][p * 2 + 0], aH[mt], &bL[p][0]);
                    mma_bf16(acc[mt][p * 2 + 1], aH[mt], &bL[p][2]);
                }
        }

        stOff += STAGE2; if (stOff == 3 * STAGE2) stOff = 0;
        wrOff += STAGE2; if (wrOff == 3 * STAGE2) wrOff = 0;
    }

    const float deps2 = (float)D_EMB * EPS_F * EPS_F;
    #pragma unroll
    for (int mt = 0; mt < 2; mt++) {
        const int r0 = blockRow + warpM * 32 + mt * 16 + (l >> 2);
        const float q2a = g_q2[r0],     qsa = g_qs[r0];
        const float q2b = g_q2[r0 + 8], qsb = g_qs[r0 + 8];
        #pragma unroll
        for (int nt = 0; nt < 8; nt++) {
            const int c0 = warpN * 64 + nt * 8 + (l & 3) * 2;
            #pragma unroll
            for (int jj = 0; jj < 2; jj++) {
                const int c = c0 + jj;
                if (c < N_WAY) {
                    const float p2v = g_p2[c], psv = g_ps[c];
                    float sqa = q2a + p2v - 2.0f * acc[mt][nt][jj]
                              + 2.0f * EPS_F * (qsa - psv) + deps2;
                    float sqb = q2b + p2v - 2.0f * acc[mt][nt][2 + jj]
                              + 2.0f * EPS_F * (qsb - psv) + deps2;
                    out[(size_t)r0 * N_WAY + c]       = -sqrtf(fmaxf(sqa, 0.0f));
                    out[(size_t)(r0 + 8) * N_WAY + c] = -sqrtf(fmaxf(sqb, 0.0f));
                }
            }
        }
    }
}

// =====================================================================
// launch
// =====================================================================
extern "C" void kernel_launch(void* const* d_in, const int* in_sizes, int n_in,
                              void* d_out, int out_size)
{
    const float* support = (const float*)d_in[0];
    const int*   labels  = (const int*)  d_in[1];
    const float* query   = (const float*)d_in[2];
    const float* W       = (const float*)d_in[3];
    const float* b       = (const float*)d_in[4];
    float*       out     = (float*)d_out;

    cudaFuncSetAttribute(gemm_bf16x3,
                         cudaFuncAttributeMaxDynamicSharedMemorySize, GEMM_SMEM);
    cudaFuncSetAttribute(dist_mma_kernel,
                         cudaFuncAttributeMaxDynamicSharedMemorySize, DIST_SMEM);

    {
        const size_t total = (size_t)M_TOT * F_IN / 4;
        convert_A<<<(unsigned)((total + 255) / 256), 256>>>(query, support);
    }
    convert_W<<<dim3(F_IN / 32, D_EMB / 32), dim3(32, 8)>>>(W);
    build_order_kernel<<<N_WAY, 32>>>(labels);

    gemm_bf16x3<<<dim3(D_EMB / GN, M_TOT / GM), NTHR, GEMM_SMEM>>>(b);

    proto_kernel<<<128, 256>>>();
    qstats_kernel<<<N_QUERY / 8, 256>>>();
    dist_mma_kernel<<<N_QUERY / 128, 256, DIST_SMEM>>>(out);
}